// round 16
// baseline (speedup 1.0000x reference)
#include <cuda_runtime.h>
#include <cuda_fp16.h>
#include <math.h>
#include <stdint.h>

// ---------------------------------------------------------------------------
// Problem constants
// ---------------------------------------------------------------------------
#define BATCH   512
#define IN_DIM  256
#define OUT_DIM 256
#define NB      11
#define FPI     12
#define KDIM    (IN_DIM*FPI)     // 3072

// GEMM config: one exact wave (4 x 4 x 8 = 128 CTAs)
#define BM 128
#define BN 64
#define BK 64
#define SK 8
#define KPC (KDIM/SK)            // 384
#define NCH (KPC/BK)             // 6 chunks, all resident in smem

#define ACHUNK 16384             // 128 rows x 128B
#define BCHUNK 8192              // 64 rows x 128B
#define ASZ (NCH*ACHUNK)         // 98304
#define BSZ (NCH*BCHUNK)         // 49152
#define TILE_SMEM (ASZ + BSZ)    // 147456
#define SCOEF_FLOATS (2*IN_DIM*NB)        // 5632 (two coef rows)
#define SMEM_TOTAL (TILE_SMEM + SCOEF_FLOATS*4)  // 169984
#define EPI_STRIDE 68

#define NTHREADS 512

// Scratch (device globals)
__device__ __half g_A[(size_t)BATCH   * KDIM];  // 3.1 MB
__device__ __half g_B[(size_t)OUT_DIM * KDIM];  // 1.5 MB
__device__ int    g_band[4];                     // per-band prep counters (target 32)
__device__ int    g_done;                        // CTAs past their wait (reset trigger)

// ---------------------------------------------------------------------------
// helpers
// ---------------------------------------------------------------------------
__device__ __forceinline__ uint32_t smem_u32(const void* p) {
    uint32_t a;
    asm("{ .reg .u64 t; cvta.to.shared.u64 t, %1; cvt.u32.u64 %0, t; }" : "=r"(a) : "l"(p));
    return a;
}
__device__ __forceinline__ void cp_async16(uint32_t dst, const void* src) {
    asm volatile("cp.async.cg.shared.global [%0], [%1], 16;" :: "r"(dst), "l"(src));
}
__device__ __forceinline__ void cp_commit() {
    asm volatile("cp.async.commit_group;");
}
template <int N>
__device__ __forceinline__ void cp_wait() {
    asm volatile("cp.async.wait_group %0;" :: "n"(N));
}
__device__ __forceinline__ void ldsm_x4(uint32_t& r0, uint32_t& r1, uint32_t& r2, uint32_t& r3, uint32_t a) {
    asm volatile("ldmatrix.sync.aligned.m8n8.x4.shared.b16 {%0,%1,%2,%3}, [%4];"
                 : "=r"(r0), "=r"(r1), "=r"(r2), "=r"(r3) : "r"(a));
}
__device__ __forceinline__ void mma16816(float* d, const uint32_t* a, uint32_t b0, uint32_t b1) {
    asm volatile(
        "mma.sync.aligned.m16n8k16.row.col.f32.f16.f16.f32 "
        "{%0,%1,%2,%3}, {%4,%5,%6,%7}, {%8,%9}, {%0,%1,%2,%3};"
        : "+f"(d[0]), "+f"(d[1]), "+f"(d[2]), "+f"(d[3])
        : "r"(a[0]), "r"(a[1]), "r"(a[2]), "r"(a[3]), "r"(b0), "r"(b1));
}

// ---------------------------------------------------------------------------
// Fused kernel: per-CTA prep slice -> flag sync -> fp16 mma.sync GEMM -> REDs.
// grid (4,4,8) = 128 CTAs (one wave, all resident), 512 threads.
// ---------------------------------------------------------------------------
__global__ __launch_bounds__(NTHREADS, 1) void kan_kernel(const float* __restrict__ x,
                                                          const float* __restrict__ coef,
                                                          const float* __restrict__ rw,
                                                          const float* __restrict__ uw,
                                                          float* __restrict__ out)
{
    extern __shared__ __align__(1024) char smem[];
    const uint32_t sA = smem_u32(smem);
    const uint32_t sB = sA + ASZ;
    float* scoef = (float*)(smem + TILE_SMEM);   // 5632 floats

    const int tid = threadIdx.x;
    const int wid = tid >> 5;
    const int lid = tid & 31;
    const int warp_m = wid & 3;       // 0..3 -> 32-row band
    const int warp_n = wid >> 2;      // 0..3 -> 16-col band

    const int bx = blockIdx.x, by = blockIdx.y, bz = blockIdx.z;
    const int ci = bx + 4 * by + 16 * bz;          // unique 0..127

    const int n0 = bx * BN;
    const int m0 = by * BM;
    const int k00 = bz * KPC;

    // ================= PREP PHASE =================
    // ---- features: rows b in [4ci, 4ci+4), all 256 i. 2 elems/thread. ----
#pragma unroll
    for (int t = 0; t < 2; ++t) {
        const int p = tid + NTHREADS * t;          // 0..1023
        const int b = 4 * ci + (p >> 8);
        const int i = p & 255;
        const float xv = x[b * IN_DIM + i];

        float xs = (xv + 1.75f) * 4.0f;
        float fc = floorf(xs);
        int   c  = (int)fc;
        float tt = xs - fc;
        float it = 1.0f - tt;
        float t2 = tt * tt, t3 = t2 * tt;
        float w0 = it * it * it * (1.0f / 6.0f);
        float w1 = (3.0f * t3 - 6.0f * t2 + 4.0f) * (1.0f / 6.0f);
        float w2 = (-3.0f * t3 + 3.0f * t2 + 3.0f * tt + 1.0f) * (1.0f / 6.0f);
        float w3 = t3 * (1.0f / 6.0f);
        bool in_range = (c >= 0 && c <= 13);

        float f[12];
#pragma unroll
        for (int j = 0; j < 11; ++j) {
            int q = j - c + 3;
            float w = (q == 0) ? w0 : (q == 1) ? w1 : (q == 2) ? w2 : w3;
            f[j] = (in_range && q >= 0 && q <= 3) ? w : 0.0f;
        }
        f[11] = xv / (1.0f + __expf(-xv));

        union { __half h[12]; uint2 u[3]; } hv;
#pragma unroll
        for (int j = 0; j < 12; ++j) hv.h[j] = __float2half_rn(f[j]);

        uint2* s = (uint2*)&g_A[(size_t)b * KDIM + i * FPI];
#pragma unroll
        for (int j = 0; j < 3; ++j) s[j] = hv.u[j];
    }

    // ---- weights: rows o in {2ci, 2ci+1}. Stage coef contiguously. ----
    {
        const float* cb = coef + (size_t)(2 * ci) * (IN_DIM * NB);
#pragma unroll
        for (int t = 0; t < SCOEF_FLOATS / NTHREADS; ++t)   // 11 iters
            scoef[tid + NTHREADS * t] = cb[tid + NTHREADS * t];
        __syncthreads();

        const int ol = tid >> 8;                    // 0..1
        const int i  = tid & 255;
        const int o  = 2 * ci + ol;
        const int gi = o * IN_DIM + i;
        const float u = uw[gi];
        float w[12];
#pragma unroll
        for (int j = 0; j < NB; ++j) w[j] = u * scoef[ol * (IN_DIM * NB) + i * NB + j];
        w[11] = rw[gi];

        union { __half h[12]; uint2 u2[3]; } hv;
#pragma unroll
        for (int j = 0; j < 12; ++j) hv.h[j] = __float2half_rn(w[j]);

        uint2* s = (uint2*)&g_B[(size_t)o * KDIM + i * FPI];
#pragma unroll
        for (int j = 0; j < 3; ++j) s[j] = hv.u2[j];
    }

    // ---- signal own band; wait for bands (y: A rows, x: B rows) ----
    __syncthreads();
    if (tid == 0) {
        __threadfence();
        atomicAdd(&g_band[ci >> 5], 1);
        volatile int* vb = (volatile int*)g_band;
        while (vb[by] < 32 || vb[bx] < 32) { __nanosleep(64); }
        __threadfence();
        int d = atomicAdd(&g_done, 1);
        if (d == 127) {              // all 128 CTAs have passed their waits
            vb[0] = 0; vb[1] = 0; vb[2] = 0; vb[3] = 0;
            *(volatile int*)&g_done = 0;
        }
    }
    __syncthreads();

    // ================= GEMM PHASE (R14 proven) =================
    const __half* A = g_A;
    const __half* B = g_B;

#pragma unroll
    for (int c = 0; c < NCH; ++c) {
        const int kb = k00 + c * BK;
        const uint32_t stA = sA + c * ACHUNK;
        const uint32_t stB = sB + c * BCHUNK;
#pragma unroll
        for (int t = 0; t < 2; ++t) {
            const int li = tid + NTHREADS * t;
            const int r = li >> 3;
            const int cb = (li & 7) << 4;
            cp_async16(stA + r * 128 + (cb ^ ((r & 7) << 4)),
                       A + (size_t)(m0 + r) * KDIM + kb + (cb >> 1));
        }
        {
            const int r = tid >> 3;
            const int cb = (tid & 7) << 4;
            cp_async16(stB + r * 128 + (cb ^ ((r & 7) << 4)),
                       B + (size_t)(n0 + r) * KDIM + kb + (cb >> 1));
        }
        cp_commit();
    }

    float acc[2][2][4];
#pragma unroll
    for (int i = 0; i < 2; ++i)
#pragma unroll
        for (int j = 0; j < 2; ++j)
#pragma unroll
            for (int q = 0; q < 4; ++q) acc[i][j][q] = 0.0f;

#pragma unroll
    for (int c = 0; c < NCH; ++c) {
        switch (c) {
            case 0: cp_wait<5>(); break;
            case 1: cp_wait<4>(); break;
            case 2: cp_wait<3>(); break;
            case 3: cp_wait<2>(); break;
            case 4: cp_wait<1>(); break;
            default: cp_wait<0>(); break;
        }
        __syncthreads();
        const uint32_t stA = sA + c * ACHUNK;
        const uint32_t stB = sB + c * BCHUNK;

#pragma unroll
        for (int ks = 0; ks < 4; ++ks) {
            uint32_t af[2][4];
#pragma unroll
            for (int mt = 0; mt < 2; ++mt) {
                const int r = warp_m * 32 + mt * 16 + (lid & 15);
                const int cb = ks * 32 + ((lid >> 4) << 4);
                ldsm_x4(af[mt][0], af[mt][1], af[mt][2], af[mt][3],
                        stA + r * 128 + (cb ^ ((r & 7) << 4)));
            }
            uint32_t bf[4];
            {
                const int r = warp_n * 16 + (lid & 7) + ((lid >> 4) << 3);
                const int cb = ks * 32 + (((lid >> 3) & 1) << 4);
                ldsm_x4(bf[0], bf[1], bf[2], bf[3],
                        stB + r * 128 + (cb ^ ((r & 7) << 4)));
            }
#pragma unroll
            for (int mt = 0; mt < 2; ++mt) {
                mma16816(acc[mt][0], af[mt], bf[0], bf[1]);
                mma16816(acc[mt][1], af[mt], bf[2], bf[3]);
            }
        }
    }

    // ---- epilogue: stage fp32 tile in smem, then float4 vector REDs ----
    __syncthreads();
    float* stile = (float*)smem;   // [128][EPI_STRIDE] = 34816 B
    {
        const int r0 = warp_m * 32 + (lid >> 2);
        const int c0 = warp_n * 16 + (lid & 3) * 2;
#pragma unroll
        for (int mt = 0; mt < 2; ++mt) {
#pragma unroll
            for (int j = 0; j < 2; ++j) {
                const int rr = r0 + mt * 16;
                const int cc = c0 + j * 8;
                stile[rr * EPI_STRIDE + cc]           = acc[mt][j][0];
                stile[rr * EPI_STRIDE + cc + 1]       = acc[mt][j][1];
                stile[(rr + 8) * EPI_STRIDE + cc]     = acc[mt][j][2];
                stile[(rr + 8) * EPI_STRIDE + cc + 1] = acc[mt][j][3];
            }
        }
    }
    __syncthreads();
#pragma unroll
    for (int q = 0; q < 4; ++q) {
        const int li = tid + NTHREADS * q;   // 0..2047 float4 slots
        const int r  = li >> 4;
        const int cq = (li & 15) << 2;
        const float4 v = *(const float4*)&stile[r * EPI_STRIDE + cq];
        atomicAdd((float4*)&out[(size_t)(m0 + r) * OUT_DIM + n0 + cq], v);
    }
}

// ---------------------------------------------------------------------------
// Launch
// ---------------------------------------------------------------------------
extern "C" void kernel_launch(void* const* d_in, const int* in_sizes, int n_in,
                              void* d_out, int out_size)
{
    const float* x    = (const float*)d_in[0];
    const float* coef = (const float*)d_in[1];
    const float* rw   = (const float*)d_in[2];
    const float* uw   = (const float*)d_in[3];
    float* out = (float*)d_out;

    cudaFuncSetAttribute(kan_kernel, cudaFuncAttributeMaxDynamicSharedMemorySize, SMEM_TOTAL);
    cudaMemsetAsync(out, 0, (size_t)BATCH * OUT_DIM * sizeof(float));
    kan_kernel<<<dim3(OUT_DIM / BN, BATCH / BM, SK), NTHREADS, SMEM_TOTAL>>>(x, coef, rw, uw, out);
}